// round 3
// baseline (speedup 1.0000x reference)
#include <cuda_runtime.h>
#include <math.h>

#define MAX_SWEEPS 30
#define NMAT_DIM 64
#define TRI_SIZE 2080   // 64*65/2

// Compressed butterfly: reduce 32 per-lane values across a warp.
// On return, lane l holds the warp-wide sum of value index l.
__device__ __forceinline__ float butterfly_reduce32(float v[32], int lane) {
    #pragma unroll
    for (int m = 16; m >= 1; m >>= 1) {
        #pragma unroll
        for (int i = 0; i < m; i++) {
            float send = (lane & m) ? v[i] : v[i + m];
            float recv = __shfl_xor_sync(0xffffffffu, send, m);
            v[i] = ((lane & m) ? v[i + m] : v[i]) + recv;
        }
    }
    return v[0];
}

__global__ __launch_bounds__(64)
void spd_logm_kernel(const float* __restrict__ A, float* __restrict__ out)
{
    __shared__ float  sA[64 * 68];   // staged input / final W rows (pad 68 floats)
    __shared__ float2 scs[32];       // per-pair (c, s)
    __shared__ float  sred[64];      // warp-1 partial sums / alpha reuse
    __shared__ float  snorm[64];     // full column norms
    __shared__ int    s_notconv;     // sweep-level convergence flag

    const int b    = blockIdx.x;
    const int tid  = threadIdx.x;
    const int lane = tid & 31;
    const int warp = tid >> 5;

    // ---- Load matrix b into shared (coalesced float4), then rows to registers ----
    const float4* A4 = (const float4*)(A + (size_t)b * 4096);
    #pragma unroll
    for (int i = 0; i < 16; i++) {
        int idx = tid + i * 64;            // 0..1023 float4s
        float4 val = A4[idx];
        int row = idx >> 4;
        int c4  = idx & 15;
        *((float4*)(sA + row * 68) + c4) = val;
    }
    __syncthreads();

    float ar[64];                          // thread tid owns row tid of W (starts = A row)
    #pragma unroll
    for (int j = 0; j < 64; j++) ar[j] = sA[tid * 68 + j];

    float npp = 0.f, nqq = 0.f;            // column-norm^2 at positions 2k,2k+1 (warp 0 only)

    for (int sweep = 0; sweep < MAX_SWEEPS; sweep++) {
        // ---- Refresh column norms (Gram diagonal) ----
        {
            float v[32];
            #pragma unroll
            for (int k = 0; k < 32; k++) v[k] = ar[k] * ar[k];
            float r0 = butterfly_reduce32(v, lane);
            #pragma unroll
            for (int k = 0; k < 32; k++) v[k] = ar[32 + k] * ar[32 + k];
            float r1 = butterfly_reduce32(v, lane);
            if (warp == 1) { sred[lane] = r0; sred[32 + lane] = r1; }
            __syncthreads();
            if (warp == 0) {
                snorm[lane]      = r0 + sred[lane];
                snorm[32 + lane] = r1 + sred[32 + lane];
            }
            if (tid == 0) s_notconv = 0;   // reset flag (ordered by next sync)
            __syncthreads();
            if (warp == 0) {
                npp = snorm[2 * lane];
                nqq = snorm[2 * lane + 1];
            }
        }

        // ---- 63 systolic rounds: pairs are always positions (2k, 2k+1) ----
        for (int round = 0; round < 63; round++) {
            // Gram off-diagonals for the 32 pairs
            float v[32];
            #pragma unroll
            for (int k = 0; k < 32; k++) v[k] = ar[2 * k] * ar[2 * k + 1];
            float g = butterfly_reduce32(v, lane);
            if (warp == 1) sred[lane] = g;
            __syncthreads();

            if (warp == 0) {
                float gpq = g + sred[lane];
                float c = 1.f, s = 0.f;
                // not-converged test: |gpq| > ~3e-6 * geomean(norms)
                unsigned big = __ballot_sync(0xffffffffu,
                                             gpq * gpq > 1e-11f * npp * nqq);
                if (lane == 0 && big) s_notconv = 1;
                if (gpq * gpq > 1e-24f * npp * nqq) {
                    float tau = 0.5f * (nqq - npp) / gpq;
                    float tt  = 1.f / (fabsf(tau) + sqrtf(1.f + tau * tau));
                    float t   = copysignf(tt, tau);
                    c = rsqrtf(1.f + t * t);
                    s = t * c;
                    npp -= t * gpq;
                    nqq += t * gpq;
                }
                scs[lane] = make_float2(c, s);
                // Permute maintained norms along with the upcoming column permutation
                float a_up  = __shfl_up_sync(0xffffffffu, npp, 1);
                float b_up  = __shfl_up_sync(0xffffffffu, nqq, 1);
                float d_dn  = __shfl_down_sync(0xffffffffu, nqq, 1);
                float npp2 = (lane == 0) ? npp : ((lane == 1) ? b_up : a_up);
                float nqq2 = (lane == 31) ? npp : d_dn;
                npp = npp2; nqq = nqq2;
            }
            __syncthreads();

            // Apply 32 rotations locally (static register indices)
            #pragma unroll
            for (int k = 0; k < 32; k++) {
                float2 cs = scs[k];
                float x = ar[2 * k], y = ar[2 * k + 1];
                ar[2 * k]     = cs.x * x - cs.y * y;
                ar[2 * k + 1] = cs.y * x + cs.x * y;
            }

            // Brent-Luk systolic permutation (static MOV chain):
            // pos0 fixed; pos2<-pos1; pos2k<-pos2k-2; pos2k+1<-pos2k+3; pos63<-pos62
            float save62 = ar[62];
            #pragma unroll
            for (int k = 31; k >= 2; k--) ar[2 * k] = ar[2 * k - 2];
            ar[2] = ar[1];
            #pragma unroll
            for (int k = 1; k <= 31; k++) ar[2 * k - 1] = ar[2 * k + 1];
            ar[63] = save62;
        }

        // Early exit: last round's flag write is ordered by its __syncthreads.
        if (!s_notconv) break;
    }

    // ---- Final column norms (= eigenvalues sigma^2, any order) ----
    {
        float v[32];
        #pragma unroll
        for (int k = 0; k < 32; k++) v[k] = ar[k] * ar[k];
        float r0 = butterfly_reduce32(v, lane);
        #pragma unroll
        for (int k = 0; k < 32; k++) v[k] = ar[32 + k] * ar[32 + k];
        float r1 = butterfly_reduce32(v, lane);
        if (warp == 1) { sred[lane] = r0; sred[32 + lane] = r1; }
        __syncthreads();
        if (warp == 0) {
            snorm[lane]      = r0 + sred[lane];
            snorm[32 + lane] = r1 + sred[32 + lane];
        }
        __syncthreads();
    }

    // ---- alpha_j = log(sigma_j)/sigma_j^2 = 0.5*ln(g_jj)/g_jj ; stage W rows to smem ----
    {
        float gjj = snorm[tid];
        sred[tid] = 0.5f * logf(gjj) / gjj;   // sred reused as alpha[64]
        #pragma unroll
        for (int j = 0; j < 64; j++) sA[tid * 68 + j] = ar[j];
    }
    __syncthreads();

    // Locally scaled row: arsc[j] = W[tid][j] * alpha[j]
    float arsc[64];
    #pragma unroll
    for (int j = 0; j < 64; j++) arsc[j] = ar[j] * sred[j];

    // logm[tid][c] = sum_j arsc[j] * W[c][j]  (broadcast reads of sA row c)
    float* outp = out + (size_t)b * TRI_SIZE;
    int base = tid * 64 - (tid * (tid - 1)) / 2 - tid;   // row-major upper-tri offset
    for (int c = 0; c < 64; c++) {
        const float4* rowc = (const float4*)(sA + c * 68);
        float acc = 0.f;
        #pragma unroll
        for (int j4 = 0; j4 < 16; j4++) {
            float4 w = rowc[j4];
            acc += arsc[4 * j4 + 0] * w.x + arsc[4 * j4 + 1] * w.y
                 + arsc[4 * j4 + 2] * w.z + arsc[4 * j4 + 3] * w.w;
        }
        if (c >= tid) outp[base + c] = acc;
    }
}

extern "C" void kernel_launch(void* const* d_in, const int* in_sizes, int n_in,
                              void* d_out, int out_size) {
    const float* A = (const float*)d_in[0];
    float* out = (float*)d_out;
    int B = in_sizes[0] / (NMAT_DIM * NMAT_DIM);
    spd_logm_kernel<<<B, 64>>>(A, out);
}

// round 4
// speedup vs baseline: 1.1007x; 1.1007x over previous
#include <cuda_runtime.h>
#include <math.h>

#define MAX_SWEEPS 30
#define NMAT_DIM 64
#define TRI_SIZE 2080   // 64*65/2

// Compressed butterfly tail: reduce 16 per-lane values (levels 8,4,2,1).
// After the preceding level-16 step, lane l ends holding the warp-wide sum
// of value index l.
#define BFLY_TAIL16(w, lane)                                            \
    {                                                                   \
        _Pragma("unroll")                                               \
        for (int m = 8; m >= 1; m >>= 1) {                              \
            _Pragma("unroll")                                           \
            for (int i = 0; i < m; i++) {                               \
                float send = ((lane) & m) ? (w)[i] : (w)[i + m];        \
                float keep = ((lane) & m) ? (w)[i + m] : (w)[i];        \
                (w)[i] = keep + __shfl_xor_sync(0xffffffffu, send, m);  \
            }                                                           \
        }                                                               \
    }

__global__ __launch_bounds__(64, 8)
void spd_logm_kernel(const float* __restrict__ A, float* __restrict__ out)
{
    __shared__ float  sA[64 * 68];   // staged input / final W rows (pad 68 floats)
    __shared__ float4 scs4[16];      // 32 (c,s) pairs packed as float4
    __shared__ float  sred[64];      // warp-1 partial sums / alpha reuse
    __shared__ float  snorm[64];     // full column norms
    __shared__ int    s_notconv;     // sweep-level convergence flag

    const int b    = blockIdx.x;
    const int tid  = threadIdx.x;
    const int lane = tid & 31;
    const int warp = tid >> 5;

    // ---- Load matrix b into shared (coalesced float4), then rows to registers ----
    const float4* A4 = (const float4*)(A + (size_t)b * 4096);
    #pragma unroll
    for (int i = 0; i < 16; i++) {
        int idx = tid + i * 64;            // 0..1023 float4s
        float4 val = A4[idx];
        int row = idx >> 4;
        int c4  = idx & 15;
        *((float4*)(sA + row * 68) + c4) = val;
    }
    __syncthreads();

    float ar[64];                          // thread tid owns row tid of W
    #pragma unroll
    for (int j = 0; j < 64; j++) ar[j] = sA[tid * 68 + j];

    float npp = 0.f, nqq = 0.f;            // column-norm^2 at positions 2k,2k+1 (warp 0)

    for (int sweep = 0; sweep < MAX_SWEEPS; sweep++) {
        // ---- Refresh column norms (Gram diagonal), streamed level-16 ----
        {
            float w[16];
            #pragma unroll
            for (int i = 0; i < 16; i++) {
                float a = ar[i] * ar[i];
                float c = ar[i + 16] * ar[i + 16];
                float send = (lane & 16) ? a : c;
                float keep = (lane & 16) ? c : a;
                w[i] = keep + __shfl_xor_sync(0xffffffffu, send, 16);
            }
            BFLY_TAIL16(w, lane);
            float r0 = w[0];
            #pragma unroll
            for (int i = 0; i < 16; i++) {
                float a = ar[i + 32] * ar[i + 32];
                float c = ar[i + 48] * ar[i + 48];
                float send = (lane & 16) ? a : c;
                float keep = (lane & 16) ? c : a;
                w[i] = keep + __shfl_xor_sync(0xffffffffu, send, 16);
            }
            BFLY_TAIL16(w, lane);
            float r1 = w[0];
            if (warp == 1) { sred[lane] = r0; sred[32 + lane] = r1; }
            __syncthreads();
            if (warp == 0) {
                snorm[lane]      = r0 + sred[lane];
                snorm[32 + lane] = r1 + sred[32 + lane];
            }
            if (tid == 0) s_notconv = 0;   // reset flag (ordered by next sync)
            __syncthreads();
            if (warp == 0) {
                npp = snorm[2 * lane];
                nqq = snorm[2 * lane + 1];
            }
        }

        // ---- 63 systolic rounds: pairs are always positions (2k, 2k+1) ----
        for (int round = 0; round < 63; round++) {
            // Gram off-diagonals for the 32 pairs, streamed level-16
            float w[16];
            #pragma unroll
            for (int i = 0; i < 16; i++) {
                float a = ar[2 * i]      * ar[2 * i + 1];
                float c = ar[2 * i + 32] * ar[2 * i + 33];
                float send = (lane & 16) ? a : c;
                float keep = (lane & 16) ? c : a;
                w[i] = keep + __shfl_xor_sync(0xffffffffu, send, 16);
            }
            BFLY_TAIL16(w, lane);
            float g = w[0];
            if (warp == 1) sred[lane] = g;
            __syncthreads();

            if (warp == 0) {
                float gpq = g + sred[lane];
                float c = 1.f, s = 0.f;
                // not-converged test: |gpq| > ~6e-5 * geomean(norms)
                unsigned big = __ballot_sync(0xffffffffu,
                                             gpq * gpq > 4e-9f * npp * nqq);
                if (lane == 0 && big) s_notconv = 1;
                if (gpq * gpq > 1e-24f * npp * nqq) {
                    float tau = 0.5f * (nqq - npp) / gpq;
                    float tt  = 1.f / (fabsf(tau) + sqrtf(1.f + tau * tau));
                    float t   = copysignf(tt, tau);
                    c = rsqrtf(1.f + t * t);
                    s = t * c;
                    npp -= t * gpq;
                    nqq += t * gpq;
                }
                ((float2*)scs4)[lane] = make_float2(c, s);
                // Permute maintained norms along with the column permutation
                float a_up  = __shfl_up_sync(0xffffffffu, npp, 1);
                float b_up  = __shfl_up_sync(0xffffffffu, nqq, 1);
                float d_dn  = __shfl_down_sync(0xffffffffu, nqq, 1);
                float npp2 = (lane == 0) ? npp : ((lane == 1) ? b_up : a_up);
                float nqq2 = (lane == 31) ? npp : d_dn;
                npp = npp2; nqq = nqq2;
            }
            __syncthreads();

            // Apply 32 rotations locally; coefficients via 16 x LDS.128
            #pragma unroll
            for (int i = 0; i < 16; i++) {
                float4 q = scs4[i];
                float x0 = ar[4 * i],     y0 = ar[4 * i + 1];
                ar[4 * i]     = q.x * x0 - q.y * y0;
                ar[4 * i + 1] = q.y * x0 + q.x * y0;
                float x1 = ar[4 * i + 2], y1 = ar[4 * i + 3];
                ar[4 * i + 2] = q.z * x1 - q.w * y1;
                ar[4 * i + 3] = q.w * x1 + q.z * y1;
            }

            // Brent-Luk systolic permutation (static MOV chain)
            float save62 = ar[62];
            #pragma unroll
            for (int k = 31; k >= 2; k--) ar[2 * k] = ar[2 * k - 2];
            ar[2] = ar[1];
            #pragma unroll
            for (int k = 1; k <= 31; k++) ar[2 * k - 1] = ar[2 * k + 1];
            ar[63] = save62;
        }

        // Early exit: last round's flag write is ordered by its __syncthreads.
        if (!s_notconv) break;
    }

    // ---- Final column norms (= eigenvalues sigma^2, any order) ----
    {
        float w[16];
        #pragma unroll
        for (int i = 0; i < 16; i++) {
            float a = ar[i] * ar[i];
            float c = ar[i + 16] * ar[i + 16];
            float send = (lane & 16) ? a : c;
            float keep = (lane & 16) ? c : a;
            w[i] = keep + __shfl_xor_sync(0xffffffffu, send, 16);
        }
        BFLY_TAIL16(w, lane);
        float r0 = w[0];
        #pragma unroll
        for (int i = 0; i < 16; i++) {
            float a = ar[i + 32] * ar[i + 32];
            float c = ar[i + 48] * ar[i + 48];
            float send = (lane & 16) ? a : c;
            float keep = (lane & 16) ? c : a;
            w[i] = keep + __shfl_xor_sync(0xffffffffu, send, 16);
        }
        BFLY_TAIL16(w, lane);
        float r1 = w[0];
        if (warp == 1) { sred[lane] = r0; sred[32 + lane] = r1; }
        __syncthreads();
        if (warp == 0) {
            snorm[lane]      = r0 + sred[lane];
            snorm[32 + lane] = r1 + sred[32 + lane];
        }
        __syncthreads();
    }

    // ---- alpha_j = 0.5*ln(g_jj)/g_jj ; stage W rows to smem ----
    {
        float gjj = snorm[tid];
        sred[tid] = 0.5f * logf(gjj) / gjj;   // sred reused as alpha[64]
        #pragma unroll
        for (int j = 0; j < 64; j++) sA[tid * 68 + j] = ar[j];
    }
    __syncthreads();

    // Scale own row in place: ar[j] = W[tid][j] * alpha[j]  (no second array)
    #pragma unroll
    for (int j = 0; j < 64; j++) ar[j] *= sred[j];

    // logm[tid][c] = sum_j ar[j] * W[c][j]  (broadcast reads of sA row c)
    float* outp = out + (size_t)b * TRI_SIZE;
    int base = tid * 64 - (tid * (tid - 1)) / 2 - tid;   // row-major upper-tri offset
    for (int c = 0; c < 64; c++) {
        const float4* rowc = (const float4*)(sA + c * 68);
        float acc = 0.f;
        #pragma unroll
        for (int j4 = 0; j4 < 16; j4++) {
            float4 w = rowc[j4];
            acc += ar[4 * j4 + 0] * w.x + ar[4 * j4 + 1] * w.y
                 + ar[4 * j4 + 2] * w.z + ar[4 * j4 + 3] * w.w;
        }
        if (c >= tid) outp[base + c] = acc;
    }
}

extern "C" void kernel_launch(void* const* d_in, const int* in_sizes, int n_in,
                              void* d_out, int out_size) {
    const float* A = (const float*)d_in[0];
    float* out = (float*)d_out;
    int B = in_sizes[0] / (NMAT_DIM * NMAT_DIM);
    spd_logm_kernel<<<B, 64>>>(A, out);
}

// round 6
// speedup vs baseline: 1.1220x; 1.0194x over previous
#include <cuda_runtime.h>
#include <math.h>

#define MAX_SWEEPS 30
#define NMAT_DIM 64
#define TRI_SIZE 2080   // 64*65/2

// Compressed butterfly tail: reduce 16 per-lane values (levels 8,4,2,1).
#define BFLY_TAIL16(w, lane)                                            \
    {                                                                   \
        _Pragma("unroll")                                               \
        for (int m = 8; m >= 1; m >>= 1) {                              \
            _Pragma("unroll")                                           \
            for (int i = 0; i < m; i++) {                               \
                float send = ((lane) & m) ? (w)[i] : (w)[i + m];        \
                float keep = ((lane) & m) ? (w)[i + m] : (w)[i];        \
                (w)[i] = keep + __shfl_xor_sync(0xffffffffu, send, m);  \
            }                                                           \
        }                                                               \
    }

__global__ __launch_bounds__(64, 8)
void spd_logm_kernel(const float* __restrict__ A, float* __restrict__ out)
{
    __shared__ float  sA[64 * 68];   // staged input / final W rows (pad 68)
    __shared__ float4 scs4[16];      // 32 (beta,gamma) pairs packed as float4
    __shared__ float  sred[64];      // warp-1 published partial sums
    __shared__ float  snorm[64];     // full column norms
    __shared__ float4 sd4[16];       // per-column fold-back scales
    __shared__ float  salpha[64];    // alpha per column (epilogue)
    __shared__ int    s_notconv;

    const int b    = blockIdx.x;
    const int tid  = threadIdx.x;
    const int lane = tid & 31;
    const int warp = tid >> 5;
    float* sd = (float*)sd4;

    // ---- Load matrix b into shared (coalesced float4), then rows to regs ----
    const float4* A4 = (const float4*)(A + (size_t)b * 4096);
    #pragma unroll
    for (int i = 0; i < 16; i++) {
        int idx = tid + i * 64;
        float4 val = A4[idx];
        int row = idx >> 4;
        int c4  = idx & 15;
        *((float4*)(sA + row * 68) + c4) = val;
    }
    __syncthreads();

    float ar[64];                    // thread tid owns row tid of stored W
    #pragma unroll
    for (int j = 0; j < 64; j++) ar[j] = sA[tid * 68 + j];

    float hnpp = 0.f, hnqq = 0.f;    // stored-data norms^2 at pos (2k,2k+1), warp0
    float dp = 1.f, dq = 1.f;        // column scale factors at pos (2k,2k+1), warp0

// One systolic round with scaled fast rotations.
#define ROUND_BODY do {                                                        \
    float w[16];                                                               \
    _Pragma("unroll")                                                          \
    for (int i = 0; i < 16; i++) {                                             \
        float a = ar[2*i]      * ar[2*i+1];                                    \
        float c = ar[2*i + 32] * ar[2*i + 33];                                 \
        float send = (lane & 16) ? a : c;                                      \
        float keep = (lane & 16) ? c : a;                                      \
        w[i] = keep + __shfl_xor_sync(0xffffffffu, send, 16);                  \
    }                                                                          \
    BFLY_TAIL16(w, lane);                                                      \
    if (warp == 1) sred[lane] = w[0];                                          \
    __syncthreads();                                                           \
    if (warp == 0) {                                                           \
        float gpq = w[0] + sred[lane];                                         \
        float beta = 0.f, gamma = 0.f;                                         \
        unsigned big = __ballot_sync(0xffffffffu,                              \
                                     gpq*gpq > 4e-9f * hnpp * hnqq);           \
        if (lane == 0 && big) s_notconv = 1;                                   \
        if (gpq*gpq > 1e-24f * hnpp * hnqq) {                                  \
            float r   = __fdividef(dq, dp);                                    \
            float ir  = __fdividef(dp, dq);                                    \
            float tau = (hnqq*r - hnpp*ir) * __fdividef(0.5f, gpq);            \
            float at  = fabsf(tau);                                            \
            float tt  = __fdividef(1.f, at + sqrtf(fmaf(at, at, 1.f)));        \
            float t   = copysignf(tt, tau);                                    \
            float one_t2 = fmaf(t, t, 1.f);                                    \
            float cc  = rsqrtf(one_t2);                                        \
            beta  = -t * r;                                                    \
            gamma =  t * ir;                                                   \
            hnpp = (hnpp + beta  * gpq) * one_t2;                              \
            hnqq = (hnqq + gamma * gpq) * one_t2;                              \
            dp *= cc; dq *= cc;                                                \
        }                                                                      \
        ((float2*)scs4)[lane] = make_float2(beta, gamma);                      \
        float a_up = __shfl_up_sync(0xffffffffu, hnpp, 1);                     \
        float b_up = __shfl_up_sync(0xffffffffu, hnqq, 1);                     \
        float d_dn = __shfl_down_sync(0xffffffffu, hnqq, 1);                   \
        float npp2 = (lane == 0) ? hnpp : ((lane == 1) ? b_up : a_up);         \
        float nqq2 = (lane == 31) ? hnpp : d_dn;                               \
        float pu = __shfl_up_sync(0xffffffffu, dp, 1);                         \
        float qu = __shfl_up_sync(0xffffffffu, dq, 1);                         \
        float qd = __shfl_down_sync(0xffffffffu, dq, 1);                       \
        float dp2 = (lane == 0) ? dp : ((lane == 1) ? qu : pu);                \
        float dq2 = (lane == 31) ? dp : qd;                                    \
        hnpp = npp2; hnqq = nqq2; dp = dp2; dq = dq2;                          \
    }                                                                          \
    __syncthreads();                                                           \
    _Pragma("unroll")                                                          \
    for (int i = 0; i < 16; i++) {                                             \
        float4 q = scs4[i];                                                    \
        float x0 = ar[4*i],   y0 = ar[4*i+1];                                  \
        ar[4*i]   = fmaf(q.x, y0, x0);                                         \
        ar[4*i+1] = fmaf(q.y, x0, y0);                                         \
        float x1 = ar[4*i+2], y1 = ar[4*i+3];                                  \
        ar[4*i+2] = fmaf(q.z, y1, x1);                                         \
        ar[4*i+3] = fmaf(q.w, x1, y1);                                         \
    }                                                                          \
    { float save62 = ar[62];                                                   \
      _Pragma("unroll")                                                        \
      for (int k = 31; k >= 2; k--) ar[2*k] = ar[2*k-2];                       \
      ar[2] = ar[1];                                                           \
      _Pragma("unroll")                                                        \
      for (int k = 1; k <= 31; k++) ar[2*k-1] = ar[2*k+1];                     \
      ar[63] = save62; }                                                       \
} while(0)

    for (int sweep = 0; sweep < MAX_SWEEPS; sweep++) {
        // ---- Refresh column norms (data is true: scales folded back) ----
        {
            float w[16];
            #pragma unroll
            for (int i = 0; i < 16; i++) {
                float a = ar[i] * ar[i];
                float c = ar[i + 16] * ar[i + 16];
                float send = (lane & 16) ? a : c;
                float keep = (lane & 16) ? c : a;
                w[i] = keep + __shfl_xor_sync(0xffffffffu, send, 16);
            }
            BFLY_TAIL16(w, lane);
            float r0 = w[0];
            #pragma unroll
            for (int i = 0; i < 16; i++) {
                float a = ar[i + 32] * ar[i + 32];
                float c = ar[i + 48] * ar[i + 48];
                float send = (lane & 16) ? a : c;
                float keep = (lane & 16) ? c : a;
                w[i] = keep + __shfl_xor_sync(0xffffffffu, send, 16);
            }
            BFLY_TAIL16(w, lane);
            float r1 = w[0];
            if (warp == 1) { sred[lane] = r0; sred[32 + lane] = r1; }
            if (tid == 0) s_notconv = 0;
            __syncthreads();
            if (warp == 0) {
                snorm[lane]      = r0 + sred[lane];
                snorm[32 + lane] = r1 + sred[32 + lane];
            }
            __syncthreads();
            if (warp == 0) {
                hnpp = snorm[2 * lane];
                hnqq = snorm[2 * lane + 1];
                dp = 1.f; dq = 1.f;
            }
        }

        // ---- 63 systolic rounds, unrolled x7 (perm absorbed by copy-prop) ----
        for (int rb = 0; rb < 9; rb++) {
            ROUND_BODY; ROUND_BODY; ROUND_BODY; ROUND_BODY;
            ROUND_BODY; ROUND_BODY; ROUND_BODY;
        }

        // ---- Fold scales back into data (positions are identity after 63) ----
        if (warp == 0) { sd[2 * lane] = dp; sd[2 * lane + 1] = dq; }
        __syncthreads();
        #pragma unroll
        for (int j = 0; j < 16; j++) {
            float4 dv = sd4[j];
            ar[4*j]   *= dv.x; ar[4*j+1] *= dv.y;
            ar[4*j+2] *= dv.z; ar[4*j+3] *= dv.w;
        }

        if (!s_notconv) break;
    }

    // ---- Final column norms (= sigma^2) ----
    {
        float w[16];
        #pragma unroll
        for (int i = 0; i < 16; i++) {
            float a = ar[i] * ar[i];
            float c = ar[i + 16] * ar[i + 16];
            float send = (lane & 16) ? a : c;
            float keep = (lane & 16) ? c : a;
            w[i] = keep + __shfl_xor_sync(0xffffffffu, send, 16);
        }
        BFLY_TAIL16(w, lane);
        float r0 = w[0];
        #pragma unroll
        for (int i = 0; i < 16; i++) {
            float a = ar[i + 32] * ar[i + 32];
            float c = ar[i + 48] * ar[i + 48];
            float send = (lane & 16) ? a : c;
            float keep = (lane & 16) ? c : a;
            w[i] = keep + __shfl_xor_sync(0xffffffffu, send, 16);
        }
        BFLY_TAIL16(w, lane);
        float r1 = w[0];
        if (warp == 1) { sred[lane] = r0; sred[32 + lane] = r1; }
        __syncthreads();
        if (warp == 0) {
            snorm[lane]      = r0 + sred[lane];
            snorm[32 + lane] = r1 + sred[32 + lane];
        }
        __syncthreads();
    }

    // ---- alpha_j = 0.5*ln(g_jj)/g_jj ; stage W rows to smem ----
    {
        float gjj = snorm[tid];
        salpha[tid] = 0.5f * logf(gjj) / gjj;
        #pragma unroll
        for (int j = 0; j < 64; j++) sA[tid * 68 + j] = ar[j];
    }
    __syncthreads();

    // Scale own row in place: ar[j] = W[tid][j] * alpha[j]
    #pragma unroll
    for (int j = 0; j < 64; j++) ar[j] *= salpha[j];

    // logm[tid][c] = sum_j ar[j] * W[c][j]
    float* outp = out + (size_t)b * TRI_SIZE;
    int base = tid * 64 - (tid * (tid - 1)) / 2 - tid;
    for (int c = 0; c < 64; c++) {
        const float4* rowc = (const float4*)(sA + c * 68);
        float acc = 0.f;
        #pragma unroll
        for (int j4 = 0; j4 < 16; j4++) {
            float4 w = rowc[j4];
            acc += ar[4 * j4 + 0] * w.x + ar[4 * j4 + 1] * w.y
                 + ar[4 * j4 + 2] * w.z + ar[4 * j4 + 3] * w.w;
        }
        if (c >= tid) outp[base + c] = acc;
    }
}

extern "C" void kernel_launch(void* const* d_in, const int* in_sizes, int n_in,
                              void* d_out, int out_size) {
    const float* A = (const float*)d_in[0];
    float* out = (float*)d_out;
    int B = in_sizes[0] / (NMAT_DIM * NMAT_DIM);
    spd_logm_kernel<<<B, 64>>>(A, out);
}

// round 9
// speedup vs baseline: 1.3902x; 1.2390x over previous
#include <cuda_runtime.h>
#include <math.h>

#define MAX_SWEEPS 30
#define TRI_SIZE 2080   // 64*65/2

__device__ __forceinline__ float frcp_fast(float x)  { float r; asm("rcp.approx.f32 %0, %1;"   : "=f"(r) : "f"(x)); return r; }
__device__ __forceinline__ float fsqrt_fast(float x) { float r; asm("sqrt.approx.f32 %0, %1;"  : "=f"(r) : "f"(x)); return r; }
__device__ __forceinline__ float frsqrt_fast(float x){ float r; asm("rsqrt.approx.f32 %0, %1;" : "=f"(r) : "f"(x)); return r; }

// Compressed butterfly tail (levels 8,4,2,1): after a preceding level-16 step,
// lane l ends holding the warp-wide sum of value index l in w[0].
#define BFLY_TAIL16(w, lane)                                            \
    {                                                                   \
        _Pragma("unroll")                                               \
        for (int m = 8; m >= 1; m >>= 1) {                              \
            _Pragma("unroll")                                           \
            for (int i = 0; i < m; i++) {                               \
                float send = ((lane) & m) ? (w)[i] : (w)[i + m];        \
                float keep = ((lane) & m) ? (w)[i + m] : (w)[i];        \
                (w)[i] = keep + __shfl_xor_sync(0xffffffffu, send, m);  \
            }                                                           \
        }                                                               \
    }

__global__ __launch_bounds__(32, 11)
void spd_logm_kernel(const float* __restrict__ A, float* __restrict__ out)
{
    __shared__ float  sW[64 * 36];     // load staging (64x32 pitch36) / epilogue (32 rows x pitch68)
    __shared__ float4 scsA[16];        // rotation coefs, double-buffered
    __shared__ float4 scsB[16];
    __shared__ float2 sd2[32];         // fold-back scales
    __shared__ float  salpha[64];
    __shared__ float  snorm[64];

    const int b    = blockIdx.x;
    const int lane = threadIdx.x;      // 32 threads = 1 warp = 1 matrix

    const float* Ab = A + (size_t)b * 4096;

    float rA[64];   // row `lane`
    float rB[64];   // row `63-lane`

    // ---- Load: two coalesced half-staging passes through smem ----
    #pragma unroll
    for (int h = 0; h < 2; h++) {
        #pragma unroll
        for (int it = 0; it < 16; it++) {
            int idx = lane + it * 32;          // 0..511
            int row = idx >> 3, c4 = idx & 7;
            float4 v = *(const float4*)(Ab + row * 64 + h * 32 + c4 * 4);
            *(float4*)(sW + row * 36 + c4 * 4) = v;
        }
        __syncwarp();
        #pragma unroll
        for (int t = 0; t < 8; t++) {
            float4 v = *(float4*)(sW + lane * 36 + t * 4);
            rA[h*32 + t*4 + 0] = v.x; rA[h*32 + t*4 + 1] = v.y;
            rA[h*32 + t*4 + 2] = v.z; rA[h*32 + t*4 + 3] = v.w;
            float4 u = *(float4*)(sW + (63 - lane) * 36 + t * 4);
            rB[h*32 + t*4 + 0] = u.x; rB[h*32 + t*4 + 1] = u.y;
            rB[h*32 + t*4 + 2] = u.z; rB[h*32 + t*4 + 3] = u.w;
        }
        __syncwarp();
    }

    float npp = 0.f, nqq = 0.f;        // pair-position norms (scaled repr), lane = pair idx
    float dp = 1.f, dq = 1.f, idp = 1.f, idq = 1.f;
    unsigned flag = 0;
    float4* scp = scsA;                // double-buffer pointers
    float4* scq = scsB;

#define ROUND_BODY do {                                                        \
    float w[16];                                                               \
    _Pragma("unroll")                                                          \
    for (int i = 0; i < 16; i++) {                                             \
        float a = rA[2*i] * rA[2*i+1];                                         \
        a = fmaf(rB[2*i], rB[2*i+1], a);                                       \
        float c = rA[2*i+32] * rA[2*i+33];                                     \
        c = fmaf(rB[2*i+32], rB[2*i+33], c);                                   \
        float send = (lane & 16) ? a : c;                                      \
        float keep = (lane & 16) ? c : a;                                      \
        w[i] = keep + __shfl_xor_sync(0xffffffffu, send, 16);                  \
    }                                                                          \
    BFLY_TAIL16(w, lane);                                                      \
    float gpq = w[0];                                                          \
    float beta = 0.f, gamma = 0.f;                                             \
    flag |= (gpq * gpq > 4e-9f * npp * nqq) ? 1u : 0u;                         \
    if (gpq * gpq > 1e-24f * npp * nqq) {                                      \
        float r   = dq * idp;                                                  \
        float ir  = dp * idq;                                                  \
        float tau = (nqq * r - npp * ir) * (0.5f * frcp_fast(gpq));            \
        float at  = fabsf(tau);                                                \
        float hyp = fsqrt_fast(fmaf(at, at, 1.f));                             \
        float tt  = frcp_fast(at + hyp);                                       \
        float t   = copysignf(tt, tau);                                        \
        float one_t2 = fmaf(t, t, 1.f);                                        \
        float cc  = frsqrt_fast(one_t2);                                       \
        float icc = one_t2 * cc;                                               \
        beta  = -t * r;                                                        \
        gamma =  t * ir;                                                       \
        npp = (npp + beta  * gpq) * one_t2;                                    \
        nqq = (nqq + gamma * gpq) * one_t2;                                    \
        dp *= cc; dq *= cc; idp *= icc; idq *= icc;                            \
    }                                                                          \
    ((float2*)scp)[lane] = make_float2(beta, gamma);                           \
    { /* permute pair-position state along the systolic cycle */               \
      float a_up = __shfl_up_sync(0xffffffffu, npp, 1);                        \
      float b_up = __shfl_up_sync(0xffffffffu, nqq, 1);                        \
      float d_dn = __shfl_down_sync(0xffffffffu, nqq, 1);                      \
      float npp2 = (lane == 0) ? npp : ((lane == 1) ? b_up : a_up);            \
      float nqq2 = (lane == 31) ? npp : d_dn;                                  \
      float pu = __shfl_up_sync(0xffffffffu, dp, 1);                           \
      float qu = __shfl_up_sync(0xffffffffu, dq, 1);                           \
      float qd = __shfl_down_sync(0xffffffffu, dq, 1);                         \
      float dp2 = (lane == 0) ? dp : ((lane == 1) ? qu : pu);                  \
      float dq2 = (lane == 31) ? dp : qd;                                      \
      float ipu = __shfl_up_sync(0xffffffffu, idp, 1);                         \
      float iqu = __shfl_up_sync(0xffffffffu, idq, 1);                         \
      float iqd = __shfl_down_sync(0xffffffffu, idq, 1);                       \
      float idp2 = (lane == 0) ? idp : ((lane == 1) ? iqu : ipu);              \
      float idq2 = (lane == 31) ? idp : iqd;                                   \
      npp = npp2; nqq = nqq2; dp = dp2; dq = dq2; idp = idp2; idq = idq2; }    \
    __syncwarp();  /* order coef STS before cross-lane LDS */                  \
    _Pragma("unroll")                                                          \
    for (int i = 0; i < 16; i++) {                                             \
        float4 q = scp[i];                                                     \
        float x0 = rA[4*i],   y0 = rA[4*i+1];                                  \
        rA[4*i]   = fmaf(q.x, y0, x0);                                         \
        rA[4*i+1] = fmaf(q.y, x0, y0);                                         \
        float x1 = rA[4*i+2], y1 = rA[4*i+3];                                  \
        rA[4*i+2] = fmaf(q.z, y1, x1);                                         \
        rA[4*i+3] = fmaf(q.w, x1, y1);                                         \
        float u0 = rB[4*i],   v0 = rB[4*i+1];                                  \
        rB[4*i]   = fmaf(q.x, v0, u0);                                         \
        rB[4*i+1] = fmaf(q.y, u0, v0);                                         \
        float u1 = rB[4*i+2], v1 = rB[4*i+3];                                  \
        rB[4*i+2] = fmaf(q.z, v1, u1);                                         \
        rB[4*i+3] = fmaf(q.w, u1, v1);                                         \
    }                                                                          \
    { float4* tmpp = scp; scp = scq; scq = tmpp; }                             \
    { float sv = rA[62];                                                       \
      _Pragma("unroll")                                                        \
      for (int k = 31; k >= 2; k--) rA[2*k] = rA[2*k-2];                       \
      rA[2] = rA[1];                                                           \
      _Pragma("unroll")                                                        \
      for (int k = 1; k <= 31; k++) rA[2*k-1] = rA[2*k+1];                     \
      rA[63] = sv; }                                                           \
    { float sv = rB[62];                                                       \
      _Pragma("unroll")                                                        \
      for (int k = 31; k >= 2; k--) rB[2*k] = rB[2*k-2];                       \
      rB[2] = rB[1];                                                           \
      _Pragma("unroll")                                                        \
      for (int k = 1; k <= 31; k++) rB[2*k-1] = rB[2*k+1];                     \
      rB[63] = sv; }                                                           \
} while(0)

    for (int sweep = 0; sweep < MAX_SWEEPS; sweep++) {
        // ---- Refresh column norms (true data) and redistribute to pairs ----
        {
            float w[16];
            #pragma unroll
            for (int i = 0; i < 16; i++) {
                float a = rA[i] * rA[i];      a = fmaf(rB[i], rB[i], a);
                float c = rA[i+16]*rA[i+16];  c = fmaf(rB[i+16], rB[i+16], c);
                float send = (lane & 16) ? a : c;
                float keep = (lane & 16) ? c : a;
                w[i] = keep + __shfl_xor_sync(0xffffffffu, send, 16);
            }
            BFLY_TAIL16(w, lane);
            float r0 = w[0];
            #pragma unroll
            for (int i = 0; i < 16; i++) {
                float a = rA[i+32]*rA[i+32];  a = fmaf(rB[i+32], rB[i+32], a);
                float c = rA[i+48]*rA[i+48];  c = fmaf(rB[i+48], rB[i+48], c);
                float send = (lane & 16) ? a : c;
                float keep = (lane & 16) ? c : a;
                w[i] = keep + __shfl_xor_sync(0xffffffffu, send, 16);
            }
            BFLY_TAIL16(w, lane);
            snorm[lane]      = r0;
            snorm[32 + lane] = w[0];
            __syncwarp();
            npp = snorm[2 * lane];
            nqq = snorm[2 * lane + 1];
            dp = 1.f; dq = 1.f; idp = 1.f; idq = 1.f;
            flag = 0;
        }

        // ---- 63 systolic rounds (9 x 7-unrolled; perm absorbed by copy-prop) ----
        for (int rb = 0; rb < 9; rb++) {
            ROUND_BODY; ROUND_BODY; ROUND_BODY; ROUND_BODY;
            ROUND_BODY; ROUND_BODY; ROUND_BODY;
        }

        // ---- Fold scales back (positions are identity after 63 rounds) ----
        sd2[lane] = make_float2(dp, dq);
        __syncwarp();
        #pragma unroll
        for (int j = 0; j < 16; j++) {
            float4 dv = *(float4*)(sd2 + 2 * j);
            rA[4*j]   *= dv.x; rA[4*j+1] *= dv.y;
            rA[4*j+2] *= dv.z; rA[4*j+3] *= dv.w;
            rB[4*j]   *= dv.x; rB[4*j+1] *= dv.y;
            rB[4*j+2] *= dv.z; rB[4*j+3] *= dv.w;
        }

        if (!__any_sync(0xffffffffu, flag)) break;
    }

    // ---- Final column norms -> alpha ----
    {
        float w[16];
        #pragma unroll
        for (int i = 0; i < 16; i++) {
            float a = rA[i] * rA[i];      a = fmaf(rB[i], rB[i], a);
            float c = rA[i+16]*rA[i+16];  c = fmaf(rB[i+16], rB[i+16], c);
            float send = (lane & 16) ? a : c;
            float keep = (lane & 16) ? c : a;
            w[i] = keep + __shfl_xor_sync(0xffffffffu, send, 16);
        }
        BFLY_TAIL16(w, lane);
        float g0 = w[0];
        #pragma unroll
        for (int i = 0; i < 16; i++) {
            float a = rA[i+32]*rA[i+32];  a = fmaf(rB[i+32], rB[i+32], a);
            float c = rA[i+48]*rA[i+48];  c = fmaf(rB[i+48], rB[i+48], c);
            float send = (lane & 16) ? a : c;
            float keep = (lane & 16) ? c : a;
            w[i] = keep + __shfl_xor_sync(0xffffffffu, send, 16);
        }
        BFLY_TAIL16(w, lane);
        float g1 = w[0];
        salpha[lane]      = 0.5f * __logf(g0) / g0;
        salpha[32 + lane] = 0.5f * __logf(g1) / g1;
        __syncwarp();
    }

    // ---- Epilogue: out[i][c] = sum_j (alpha_j W[i][j]) W[c][j], two c-passes ----
    float* outp = out + (size_t)b * TRI_SIZE;
    const int rowA = lane, rowB = 63 - lane;
    const int baseA = rowA * 64 - (rowA * (rowA - 1)) / 2 - rowA;
    const int baseB = rowB * 64 - (rowB * (rowB - 1)) / 2 - rowB;

    // Pass 0: stage rows 0..31 (= everyone's rA, original values)
    #pragma unroll
    for (int t = 0; t < 16; t++)
        *(float4*)(sW + lane * 68 + t * 4) =
            make_float4(rA[4*t], rA[4*t+1], rA[4*t+2], rA[4*t+3]);
    __syncwarp();
    // scale rA in place by alpha (u vector for output row `lane`)
    #pragma unroll
    for (int t = 0; t < 16; t++) {
        float4 av = *(float4*)(salpha + 4 * t);
        rA[4*t] *= av.x; rA[4*t+1] *= av.y; rA[4*t+2] *= av.z; rA[4*t+3] *= av.w;
    }
    for (int c = lane; c < 32; c++) {
        const float4* rowc = (const float4*)(sW + c * 68);
        float acc = 0.f;
        #pragma unroll
        for (int t = 0; t < 16; t++) {
            float4 wv = rowc[t];
            acc += rA[4*t]*wv.x + rA[4*t+1]*wv.y + rA[4*t+2]*wv.z + rA[4*t+3]*wv.w;
        }
        outp[baseA + c] = acc;
    }
    __syncwarp();

    // Pass 1: stage rows 32..63 (= everyone's rB, original values)
    #pragma unroll
    for (int t = 0; t < 16; t++)
        *(float4*)(sW + (31 - lane) * 68 + t * 4) =
            make_float4(rB[4*t], rB[4*t+1], rB[4*t+2], rB[4*t+3]);
    __syncwarp();
    // scale rB in place by alpha (u vector for output row `63-lane`)
    #pragma unroll
    for (int t = 0; t < 16; t++) {
        float4 av = *(float4*)(salpha + 4 * t);
        rB[4*t] *= av.x; rB[4*t+1] *= av.y; rB[4*t+2] *= av.z; rB[4*t+3] *= av.w;
    }
    for (int c = 32; c < 64; c++) {
        const float4* rowc = (const float4*)(sW + (c - 32) * 68);
        float accA = 0.f;
        #pragma unroll
        for (int t = 0; t < 16; t++) {
            float4 wv = rowc[t];
            accA += rA[4*t]*wv.x + rA[4*t+1]*wv.y + rA[4*t+2]*wv.z + rA[4*t+3]*wv.w;
        }
        outp[baseA + c] = accA;
        if (c >= rowB) {
            float accB = 0.f;
            #pragma unroll
            for (int t = 0; t < 16; t++) {
                float4 wv = rowc[t];
                accB += rB[4*t]*wv.x + rB[4*t+1]*wv.y + rB[4*t+2]*wv.z + rB[4*t+3]*wv.w;
            }
            outp[baseB + c] = accB;
        }
    }
}

extern "C" void kernel_launch(void* const* d_in, const int* in_sizes, int n_in,
                              void* d_out, int out_size) {
    const float* A = (const float*)d_in[0];
    float* out = (float*)d_out;
    int B = in_sizes[0] / 4096;
    spd_logm_kernel<<<B, 32>>>(A, out);
}